// round 13
// baseline (speedup 1.0000x reference)
#include <cuda_runtime.h>
#include <cuda_fp16.h>
#include <cstdint>

// ---------------- problem constants ----------------
#define CC   128
#define HH   96
#define WW   128
#define PP   (HH * WW)      // 12288 (M)
#define HRR  96
#define WRR  128
#define QQ   (HRR * WRR)    // 12288 (N)

// ---------------- tiling ----------------
#define BM    128
#define BN    256
#define NQT   (QQ / BN)     // 48
#define NS    3             // 288 CTAs = 2 waves @ 94.7%
#define TPC   (NQT / NS)    // 16 tiles per CTA

#define A_IMG_BYTES   32768
#define B_IMG_BYTES   65536
#define B_HALF_BYTES  32768
#define SMEM_A_OFF    1024
#define SMEM_B_OFF    (SMEM_A_OFF + A_IMG_BYTES)           // 33792
#define SMEM_TOTAL    (SMEM_B_OFF + 4 * B_HALF_BYTES)      // 164864

#define DELTA 0.08f

// ---------------- device scratch (no allocs allowed) ----------------
// A: [mt 96][s 8][mf 8][lane 32] uint4 (fp16-hi fragment-ready)
__device__ uint4 gA4[96 * 8 * 8 * 32];
// B: [qt 48][s 8][wn 4][r4 4][lane 32] uint4 (fp16-hi fragment-ready, lane-contig)
__device__ uint4 gB4[48 * 8 * 4 * 4 * 32];
// transposed fp32 copies for exact repair: [pixel][channel]
__device__ float gflT[(size_t)PP * CC];
__device__ float gfrT[(size_t)QQ * CC];
// per-(split,wn) approx top-2: {v1, q1-as-float-bits, v2, 0} — one writer per slot
__device__ float4 g_part[NS * 4 * PP];
__device__ int g_cnt;
__device__ int g_list[PP];
__device__ unsigned long long g_best[PP];

// ---------------- helpers ----------------
__device__ __forceinline__ uint32_t smem_u32(const void* p) {
    uint32_t a;
    asm("{ .reg .u64 t; cvta.to.shared.u64 t, %1; cvt.u32.u64 %0, t; }" : "=r"(a) : "l"(p));
    return a;
}
__device__ __forceinline__ unsigned int fkey(float f) {
    unsigned int b = __float_as_uint(f);
    return (b & 0x80000000u) ? ~b : (b | 0x80000000u);
}
__device__ __forceinline__ unsigned short h16(float x) {
    __half h = __float2half_rn(x);
    return *reinterpret_cast<unsigned short*>(&h);
}

// ---------------- mbarrier ----------------
#define MBAR_INIT(a, n) \
    asm volatile("mbarrier.init.shared.b64 [%0], %1;" :: "r"(a), "r"((uint32_t)(n)) : "memory")
#define MBAR_EXPECT_TX(a, n) \
    asm volatile("mbarrier.arrive.expect_tx.shared.b64 _, [%0], %1;" :: "r"(a), "r"((uint32_t)(n)) : "memory")
#define MBAR_ARRIVE(a) \
    asm volatile("mbarrier.arrive.shared.b64 _, [%0];" :: "r"(a) : "memory")

__device__ __forceinline__ void mbar_wait(uint32_t mbar, uint32_t phase) {
    asm volatile(
        "{\n\t.reg .pred P1;\n\t"
        "W_%=:\n\t"
        "mbarrier.try_wait.parity.acquire.cta.shared::cta.b64 P1, [%0], %1, 0x989680;\n\t"
        "@P1 bra.uni D_%=;\n\t"
        "bra.uni W_%=;\n\t"
        "D_%=:\n\t}"
        :: "r"(mbar), "r"(phase) : "memory");
}

__device__ __forceinline__ void issue_cp(uint32_t dst, const char* src, uint32_t fullb) {
    MBAR_EXPECT_TX(fullb, B_HALF_BYTES);
    asm volatile(
        "cp.async.bulk.shared::cluster.global.mbarrier::complete_tx::bytes "
        "[%0], [%1], %2, [%3];"
        :: "r"(dst), "l"(src), "r"((uint32_t)B_HALF_BYTES), "r"(fullb) : "memory");
}

// ---------------- legacy tensor-core mma ----------------
__device__ __forceinline__ void mma16816(float* d, uint32_t a0, uint32_t a1, uint32_t a2,
                                         uint32_t a3, uint32_t b0, uint32_t b1) {
    asm volatile(
        "mma.sync.aligned.m16n8k16.row.col.f32.f16.f16.f32 "
        "{%0,%1,%2,%3}, {%4,%5,%6,%7}, {%8,%9}, {%0,%1,%2,%3};"
        : "+f"(d[0]), "+f"(d[1]), "+f"(d[2]), "+f"(d[3])
        : "r"(a0), "r"(a1), "r"(a2), "r"(a3), "r"(b0), "r"(b1));
}

// ---------------- transpose [CC][PP] -> [PP][CC] ----------------
__global__ void transpose_kernel(float* __restrict__ dst, const float* __restrict__ src) {
    __shared__ float t[32][33];
    int bx = blockIdx.x * 32, by = blockIdx.y * 32;
    int tx = threadIdx.x, ty = threadIdx.y;
    #pragma unroll
    for (int j = 0; j < 32; j += 8)
        t[ty + j][tx] = src[(size_t)(by + ty + j) * PP + bx + tx];
    __syncthreads();
    #pragma unroll
    for (int j = 0; j < 32; j += 8)
        dst[(size_t)(bx + ty + j) * CC + by + tx] = t[tx][ty + j];
}

// ---------------- precompute: fp16-hi fragment-ready ----------------
__global__ void splitA_kernel(const float* __restrict__ fl) {
    int idx = blockIdx.x * 256 + threadIdx.x;          // 196608
    int lane = idx & 31, mf = (idx >> 5) & 7, s = (idx >> 8) & 7, mt = idx >> 11;
    int g = lane >> 2, t = lane & 3;
    int M = mt * 128 + mf * 16 + g;
    int K = s * 16 + 2 * t;
    float v[8];
    v[0] = fl[(size_t)K * PP + M];           v[1] = fl[(size_t)(K + 1) * PP + M];
    v[2] = fl[(size_t)K * PP + M + 8];       v[3] = fl[(size_t)(K + 1) * PP + M + 8];
    v[4] = fl[(size_t)(K + 8) * PP + M];     v[5] = fl[(size_t)(K + 9) * PP + M];
    v[6] = fl[(size_t)(K + 8) * PP + M + 8]; v[7] = fl[(size_t)(K + 9) * PP + M + 8];
    uint4 o;
    o.x = ((uint32_t)h16(v[1]) << 16) | h16(v[0]);
    o.y = ((uint32_t)h16(v[3]) << 16) | h16(v[2]);
    o.z = ((uint32_t)h16(v[5]) << 16) | h16(v[4]);
    o.w = ((uint32_t)h16(v[7]) << 16) | h16(v[6]);
    gA4[((((size_t)mt * 8 + s) * 8 + mf)) * 32 + lane] = o;
}

__global__ void splitB_kernel(const float* __restrict__ fr) {
    int idx = blockIdx.x * 256 + threadIdx.x;          // 196608
    int lane = idx & 31, r4 = (idx >> 5) & 3, wn = (idx >> 7) & 3;
    int s = (idx >> 9) & 7, qt = idx >> 12;
    int g = lane >> 2, t = lane & 3;
    int k0 = s * 16 + 2 * t;
    uint32_t regs[4];
    #pragma unroll
    for (int h2 = 0; h2 < 2; ++h2) {
        int j = 2 * r4 + h2;
        int n = qt * 256 + wn * 64 + j * 8 + g;
        float v0 = fr[(size_t)k0 * QQ + n];
        float v1 = fr[(size_t)(k0 + 1) * QQ + n];
        float v8 = fr[(size_t)(k0 + 8) * QQ + n];
        float v9 = fr[(size_t)(k0 + 9) * QQ + n];
        regs[2 * h2]     = ((uint32_t)h16(v1) << 16) | h16(v0);
        regs[2 * h2 + 1] = ((uint32_t)h16(v9) << 16) | h16(v8);
    }
    size_t o = ((((size_t)qt * 8 + s) * 4 + wn) * 4 + r4) * 32 + lane;
    gB4[o] = make_uint4(regs[0], regs[1], regs[2], regs[3]);
}

__global__ void init_kernel() {
    if (blockIdx.x == 0 && threadIdx.x == 0) g_cnt = 0;
}

// ---------------- compute half (1 pass over 4 k-steps) ----------------
__device__ __forceinline__ void mma_block(float* acc, const uint4 af[4], const uint4 bfm[4]) {
    #pragma unroll
    for (int i = 0; i < 4; ++i) {
        #pragma unroll
        for (int r = 0; r < 4; ++r) {
            mma16816(&acc[(i * 8 + 2 * r) * 4],
                     af[i].x, af[i].y, af[i].z, af[i].w, bfm[r].x, bfm[r].y);
            mma16816(&acc[(i * 8 + 2 * r + 1) * 4],
                     af[i].x, af[i].y, af[i].z, af[i].w, bfm[r].z, bfm[r].w);
        }
    }
}

__device__ __forceinline__ void compute_half(const uint4* A0, const uint4* Bw, float* acc) {
    #pragma unroll
    for (int s = 0; s < 4; ++s) {
        uint4 bfm[4];
        const uint4* bp = Bw + (s << 9);
        #pragma unroll
        for (int r = 0; r < 4; ++r) bfm[r] = bp[r * 32];
        uint4 af[4];
        #pragma unroll
        for (int i = 0; i < 4; ++i) af[i] = A0[(s * 8 + i) * 32];
        mma_block(acc, af, bfm);
    }
}

// fold tile's acc into running per-slot top-2, zero acc
__device__ __forceinline__ void fold_zero(float* acc, float* bv, int* bq, float* bw,
                                          int q0, int t2) {
    #pragma unroll
    for (int i = 0; i < 4; ++i)
        #pragma unroll
        for (int j = 0; j < 8; ++j) {
            int qb = q0 + j * 8 + t2;
            #pragma unroll
            for (int c = 0; c < 4; ++c) {
                float v = acc[(i * 8 + j) * 4 + c];
                int slot = i * 2 + (c >> 1);
                int q = qb + (c & 1);
                if (v > bv[slot])      { bw[slot] = bv[slot]; bv[slot] = v; bq[slot] = q; }
                else if (v > bw[slot]) { bw[slot] = v; }
                acc[(i * 8 + j) * 4 + c] = 0.0f;
            }
        }
}

// ---------------- main GEMM (1-pass fp16) + top-2 argmax ----------------
__global__ void __launch_bounds__(256, 1)
corr_mma_kernel() {
    extern __shared__ char smem[];
    const uint32_t sb = smem_u32(smem);
    const int tid = threadIdx.x, lane = tid & 31, wid = tid >> 5;
    const int wm = wid >> 2, wn = wid & 3;
    const int g = lane >> 2, t = lane & 3;
    const int mt = blockIdx.x, ns = blockIdx.y;
    const int tile0 = ns * TPC;

    const uint32_t FULL0 = sb + 0,  FULL1 = sb + 16, FULL2 = sb + 32, FULL3 = sb + 48;
    const uint32_t FREE0 = sb + 64, FREE1 = sb + 80, FREE2 = sb + 96, FREE3 = sb + 112;
    if (tid == 0) {
        MBAR_INIT(FULL0, 1); MBAR_INIT(FULL1, 1); MBAR_INIT(FULL2, 1); MBAR_INIT(FULL3, 1);
        MBAR_INIT(FREE0, 256); MBAR_INIT(FREE1, 256);
        MBAR_INIT(FREE2, 256); MBAR_INIT(FREE3, 256);
    }

    // A image (32KB) -> resident SMEM
    {
        const uint4* srcA = gA4 + (size_t)mt * 2048;
        uint4* dstA = reinterpret_cast<uint4*>(smem + SMEM_A_OFF);
        #pragma unroll
        for (int i = 0; i < 8; ++i) dstA[i * 256 + tid] = srcA[i * 256 + tid];
    }
    __syncthreads();

    const char* gb = reinterpret_cast<const char*>(gB4);
    // prologue: buf0..3 = tile0:k0, tile0:k1, tile1:k0, tile1:k1
    if (tid == 0) {
        size_t b0 = (size_t)tile0 * B_IMG_BYTES;
        issue_cp(sb + SMEM_B_OFF + 0 * B_HALF_BYTES, gb + b0,                               FULL0);
        issue_cp(sb + SMEM_B_OFF + 1 * B_HALF_BYTES, gb + b0 + B_HALF_BYTES,                FULL1);
        issue_cp(sb + SMEM_B_OFF + 2 * B_HALF_BYTES, gb + b0 + B_IMG_BYTES,                 FULL2);
        issue_cp(sb + SMEM_B_OFF + 3 * B_HALF_BYTES, gb + b0 + B_IMG_BYTES + B_HALF_BYTES,  FULL3);
    }

    const uint4* A0 = reinterpret_cast<const uint4*>(smem + SMEM_A_OFF) + (4 * wm) * 32 + lane;
    const uint4* B0 = reinterpret_cast<const uint4*>(smem + SMEM_B_OFF) + (wn << 7) + lane;
    const uint4* B1 = B0 + (B_HALF_BYTES / 16);
    const uint4* B2 = B1 + (B_HALF_BYTES / 16);
    const uint4* B3 = B2 + (B_HALF_BYTES / 16);

    float acc[128];
    float bv[8], bw[8];
    int bq[8];
    #pragma unroll
    for (int i = 0; i < 8; ++i) { bv[i] = -3.402823466e38f; bw[i] = -3.402823466e38f; bq[i] = 0; }

    const int t2 = 2 * t;

    for (int p8 = 0; p8 < 8; ++p8) {       // tile pair (2*p8, 2*p8+1)
        const uint32_t ph = (uint32_t)(p8 & 1);
        const int T0 = 2 * p8;
        const bool refill = (p8 < 7);
        const size_t nb0 = (size_t)(tile0 + T0 + 2) * B_IMG_BYTES;  // tiles T0+2, T0+3
        const size_t nb1 = nb0 + B_IMG_BYTES;

        if (p8 == 0) {
            #pragma unroll
            for (int i = 0; i < 128; ++i) acc[i] = 0.0f;
        } else {
            fold_zero(acc, bv, bq, bw, (tile0 + T0 - 1) * 256 + wn * 64, t2);
        }

        // tile T0: k0 (buf0), k1 (buf1)
        mbar_wait(FULL0, ph);
        compute_half(A0, B0, acc);
        MBAR_ARRIVE(FREE0);
        if (tid == 0 && refill) { mbar_wait(FREE0, ph);
            issue_cp(sb + SMEM_B_OFF + 0 * B_HALF_BYTES, gb + nb0, FULL0); }

        mbar_wait(FULL1, ph);
        compute_half(A0 + 1024, B1, acc);
        MBAR_ARRIVE(FREE1);
        if (tid == 0 && refill) { mbar_wait(FREE1, ph);
            issue_cp(sb + SMEM_B_OFF + 1 * B_HALF_BYTES, gb + nb0 + B_HALF_BYTES, FULL1); }

        fold_zero(acc, bv, bq, bw, (tile0 + T0) * 256 + wn * 64, t2);

        // tile T0+1: k0 (buf2), k1 (buf3)
        mbar_wait(FULL2, ph);
        compute_half(A0, B2, acc);
        MBAR_ARRIVE(FREE2);
        if (tid == 0 && refill) { mbar_wait(FREE2, ph);
            issue_cp(sb + SMEM_B_OFF + 2 * B_HALF_BYTES, gb + nb1, FULL2); }

        mbar_wait(FULL3, ph);
        compute_half(A0 + 1024, B3, acc);
        MBAR_ARRIVE(FREE3);
        if (tid == 0 && refill) { mbar_wait(FREE3, ph);
            issue_cp(sb + SMEM_B_OFF + 3 * B_HALF_BYTES, gb + nb1 + B_HALF_BYTES, FULL3); }
    }

    fold_zero(acc, bv, bq, bw, (tile0 + TPC - 1) * 256 + wn * 64, t2);

    // top-2 merge across the 4 lanes sharing each row
    #pragma unroll
    for (int off = 1; off < 4; off <<= 1) {
        #pragma unroll
        for (int s2 = 0; s2 < 8; ++s2) {
            float ov = __shfl_xor_sync(0xFFFFFFFFu, bv[s2], off);
            int oq = __shfl_xor_sync(0xFFFFFFFFu, bq[s2], off);
            float ow = __shfl_xor_sync(0xFFFFFFFFu, bw[s2], off);
            if (ov > bv[s2] || (ov == bv[s2] && oq < bq[s2])) {
                bw[s2] = fmaxf(bv[s2], ow); bv[s2] = ov; bq[s2] = oq;
            } else {
                bw[s2] = fmaxf(bw[s2], ov);
            }
        }
    }
    // RACE FIX: one slot per (ns, wn, row) — exactly one writer
    if (t == 0) {
        #pragma unroll
        for (int s2 = 0; s2 < 8; ++s2) {
            int row = mt * 128 + (4 * wm + (s2 >> 1)) * 16 + g + (s2 & 1) * 8;
            g_part[((size_t)(ns * 4 + wn)) * PP + row] =
                make_float4(bv[s2], __int_as_float(bq[s2]), bw[s2], 0.0f);
        }
    }
}

// ---------------- decode1: merge 12 partials, exact winner value, flag close rows ----------------
__global__ void decode1_kernel(float* __restrict__ out,
                               const int* __restrict__ sxp,
                               const int* __restrict__ syp) {
    int p = blockIdx.x * 8 + (threadIdx.x >> 5);
    int lane = threadIdx.x & 31;

    float v1 = -3.402823466e38f, v2 = -3.402823466e38f;
    int q1 = 0;
    #pragma unroll
    for (int k = 0; k < NS * 4; ++k) {
        float4 pa = g_part[(size_t)k * PP + p];
        float pv = pa.x; int pq = __float_as_int(pa.y); float pw = pa.z;
        if (pv > v1) {
            v2 = fmaxf(v1, pw); v1 = pv; q1 = pq;
        } else {
            if (pv == v1 && pq < q1) q1 = pq;   // ties also give margin 0 -> flagged
            v2 = fmaxf(v2, pv);
        }
    }

    // exact fp32 dot for the winner (always; exact flow_cost)
    float4 a = *reinterpret_cast<const float4*>(gflT + (size_t)p * CC + lane * 4);
    float4 b = *reinterpret_cast<const float4*>(gfrT + (size_t)q1 * CC + lane * 4);
    float s = fmaf(a.x, b.x, fmaf(a.y, b.y, fmaf(a.z, b.z, a.w * b.w)));
    #pragma unroll
    for (int off = 16; off > 0; off >>= 1) s += __shfl_xor_sync(0xFFFFFFFFu, s, off);

    if (lane == 0) {
        int sx = sxp ? *sxp : 4;
        int sy = syp ? *syp : 4;
        int h = p / WW, w = p % WW;
        int i = q1 / WRR, j = q1 % WRR;
        out[2 * p + 0]  = (float)(w - j * sx);
        out[2 * p + 1]  = (float)(h - i * sy);
        out[2 * PP + p] = s;
        if (v1 - v2 < DELTA) {
            int k = atomicAdd(&g_cnt, 1);
            g_list[k] = p;
            g_best[p] = 0ull;
        }
    }
}

// ---------------- rescan: exact full-row scan for flagged rows ----------------
// grid 48 blocks x 256 thr; block b owns q in [b*256, b*256+256)
__global__ void rescan_kernel() {
    extern __shared__ float rs[];
    float* frs = rs;                              // [256][132] padded rows
    float* fls = rs + 256 * 132;                  // [128]
    unsigned long long* sbest =
        reinterpret_cast<unsigned long long*>(rs + 256 * 132 + 128);

    int cnt = g_cnt;
    if (cnt == 0) return;
    int tid = threadIdx.x;
    int q0 = blockIdx.x * 256;

    // stage this block's 256 frT rows (coalesced)
    for (int it = 0; it < 32; ++it) {
        int gidx = it * 256 + tid;                // 8192 float4s
        int ql = gidx >> 5, c4 = gidx & 31;
        float4 v = *reinterpret_cast<const float4*>(gfrT + (size_t)(q0 + ql) * CC + c4 * 4);
        *reinterpret_cast<float4*>(frs + ql * 132 + c4 * 4) = v;
    }

    const float* myq = frs + tid * 132;
    int myqi = q0 + tid;

    for (int i = 0; i < cnt; ++i) {
        int p = g_list[i];
        __syncthreads();
        if (tid == 0) *sbest = 0ull;
        if (tid < 32)
            *reinterpret_cast<float4*>(fls + tid * 4) =
                *reinterpret_cast<const float4*>(gflT + (size_t)p * CC + tid * 4);
        __syncthreads();

        float acc = 0.0f;
        #pragma unroll 8
        for (int c4 = 0; c4 < 32; ++c4) {
            float4 a = *reinterpret_cast<const float4*>(fls + c4 * 4);
            float4 b = *reinterpret_cast<const float4*>(myq + c4 * 4);
            acc = fmaf(a.x, b.x, acc); acc = fmaf(a.y, b.y, acc);
            acc = fmaf(a.z, b.z, acc); acc = fmaf(a.w, b.w, acc);
        }
        unsigned long long pk = ((unsigned long long)fkey(acc) << 32) |
                                (0xFFFFFFFFu - (unsigned)myqi);
        atomicMax(sbest, pk);
        __syncthreads();
        if (tid == 0) atomicMax(&g_best[p], *sbest);
    }
}

// ---------------- decode2: overwrite flagged rows with exact results ----------------
__global__ void decode2_kernel(float* __restrict__ out,
                               const int* __restrict__ sxp,
                               const int* __restrict__ syp) {
    int i = blockIdx.x * blockDim.x + threadIdx.x;
    if (i >= g_cnt) return;
    int p = g_list[i];
    int sx = sxp ? *sxp : 4;
    int sy = syp ? *syp : 4;

    unsigned long long pk = g_best[p];
    unsigned int key = (unsigned int)(pk >> 32);
    unsigned int idx = 0xFFFFFFFFu - (unsigned int)(pk & 0xFFFFFFFFu);
    float val = (key & 0x80000000u) ? __uint_as_float(key ^ 0x80000000u)
                                    : __uint_as_float(~key);
    int h = p / WW, w = p % WW;
    int ii = (int)(idx / WRR), j = (int)(idx % WRR);

    out[2 * p + 0]  = (float)(w - j * sx);
    out[2 * p + 1]  = (float)(h - ii * sy);
    out[2 * PP + p] = val;
}

// ---------------- launch ----------------
extern "C" void kernel_launch(void* const* d_in, const int* in_sizes, int n_in,
                              void* d_out, int out_size) {
    const float* fl = (const float*)d_in[0];
    const float* fr = (const float*)d_in[1];
    const int* sxp = (n_in > 2) ? (const int*)d_in[2] : nullptr;
    const int* syp = (n_in > 3) ? (const int*)d_in[3] : nullptr;
    float* out = (float*)d_out;
    (void)in_sizes; (void)out_size;

    cudaFuncSetAttribute(corr_mma_kernel,
                         cudaFuncAttributeMaxDynamicSharedMemorySize, SMEM_TOTAL);
    const int RESCAN_SMEM = (256 * 132 + 128) * 4 + 16;
    cudaFuncSetAttribute(rescan_kernel,
                         cudaFuncAttributeMaxDynamicSharedMemorySize, RESCAN_SMEM);

    float* flT; cudaGetSymbolAddress((void**)&flT, gflT);
    float* frT; cudaGetSymbolAddress((void**)&frT, gfrT);

    transpose_kernel<<<dim3(PP / 32, CC / 32), dim3(32, 8)>>>(flT, fl);
    transpose_kernel<<<dim3(QQ / 32, CC / 32), dim3(32, 8)>>>(frT, fr);
    splitA_kernel<<<768, 256>>>(fl);
    splitB_kernel<<<768, 256>>>(fr);
    init_kernel<<<1, 32>>>();
    corr_mma_kernel<<<dim3(PP / BM, NS), 256, SMEM_TOTAL>>>();
    decode1_kernel<<<PP / 8, 256>>>(out, sxp, syp);
    rescan_kernel<<<48, 256, RESCAN_SMEM>>>();
    decode2_kernel<<<48, 256>>>(out, sxp, syp);
}

// round 15
// speedup vs baseline: 2.6159x; 2.6159x over previous
#include <cuda_runtime.h>
#include <cuda_fp16.h>
#include <cstdint>
#include <cfloat>

// ---------------- problem constants ----------------
#define CC   128
#define HH   96
#define WW   128
#define PP   (HH * WW)      // 12288 (M)
#define HRR  96
#define WRR  128
#define QQ   (HRR * WRR)    // 12288 (N)

// ---------------- tiling ----------------
#define BM    128
#define BN    256
#define NQT   (QQ / BN)     // 48
#define NS    3             // 288 CTAs = 2 waves @ 94.7%
#define TPC   (NQT / NS)    // 16 tiles per CTA

#define A_IMG_BYTES   32768
#define B_IMG_BYTES   65536
#define B_HALF_BYTES  32768
#define SMEM_A_OFF    1024
#define SMEM_B_OFF    (SMEM_A_OFF + A_IMG_BYTES)           // 33792
#define SMEM_TOTAL    (SMEM_B_OFF + 4 * B_HALF_BYTES)      // 164864

#define DELTA 0.10f

// ---------------- device scratch (no allocs allowed) ----------------
__device__ uint4 gA4[96 * 8 * 8 * 32];
__device__ uint4 gB4[48 * 8 * 4 * 4 * 32];
__device__ float gflT[(size_t)PP * CC];
__device__ float gfrT[(size_t)QQ * CC];
// per-(split,wn) approx top-2: {v1, q1-as-float-bits, v2, 0} — one writer per slot
__device__ float4 g_part[NS * 4 * PP];
__device__ int g_cnt;
__device__ int g_list[PP];
__device__ int g_mask[PP];
__device__ unsigned long long g_best[PP];

// ---------------- helpers ----------------
__device__ __forceinline__ uint32_t smem_u32(const void* p) {
    uint32_t a;
    asm("{ .reg .u64 t; cvta.to.shared.u64 t, %1; cvt.u32.u64 %0, t; }" : "=r"(a) : "l"(p));
    return a;
}
__device__ __forceinline__ unsigned int fkey(float f) {
    unsigned int b = __float_as_uint(f);
    return (b & 0x80000000u) ? ~b : (b | 0x80000000u);
}
__device__ __forceinline__ unsigned long long packkey(float v, int q) {
    return ((unsigned long long)fkey(v) << 32) | (0xFFFFFFFFu - (unsigned)q);
}
__device__ __forceinline__ unsigned short h16(float x) {
    __half h = __float2half_rn(x);
    return *reinterpret_cast<unsigned short*>(&h);
}

// ---------------- mbarrier ----------------
#define MBAR_INIT(a, n) \
    asm volatile("mbarrier.init.shared.b64 [%0], %1;" :: "r"(a), "r"((uint32_t)(n)) : "memory")
#define MBAR_EXPECT_TX(a, n) \
    asm volatile("mbarrier.arrive.expect_tx.shared.b64 _, [%0], %1;" :: "r"(a), "r"((uint32_t)(n)) : "memory")
#define MBAR_ARRIVE(a) \
    asm volatile("mbarrier.arrive.shared.b64 _, [%0];" :: "r"(a) : "memory")

__device__ __forceinline__ void mbar_wait(uint32_t mbar, uint32_t phase) {
    asm volatile(
        "{\n\t.reg .pred P1;\n\t"
        "W_%=:\n\t"
        "mbarrier.try_wait.parity.acquire.cta.shared::cta.b64 P1, [%0], %1, 0x989680;\n\t"
        "@P1 bra.uni D_%=;\n\t"
        "bra.uni W_%=;\n\t"
        "D_%=:\n\t}"
        :: "r"(mbar), "r"(phase) : "memory");
}

__device__ __forceinline__ void issue_cp(uint32_t dst, const char* src, uint32_t fullb) {
    MBAR_EXPECT_TX(fullb, B_HALF_BYTES);
    asm volatile(
        "cp.async.bulk.shared::cluster.global.mbarrier::complete_tx::bytes "
        "[%0], [%1], %2, [%3];"
        :: "r"(dst), "l"(src), "r"((uint32_t)B_HALF_BYTES), "r"(fullb) : "memory");
}

// ---------------- legacy tensor-core mma ----------------
__device__ __forceinline__ void mma16816(float* d, uint32_t a0, uint32_t a1, uint32_t a2,
                                         uint32_t a3, uint32_t b0, uint32_t b1) {
    asm volatile(
        "mma.sync.aligned.m16n8k16.row.col.f32.f16.f16.f32 "
        "{%0,%1,%2,%3}, {%4,%5,%6,%7}, {%8,%9}, {%0,%1,%2,%3};"
        : "+f"(d[0]), "+f"(d[1]), "+f"(d[2]), "+f"(d[3])
        : "r"(a0), "r"(a1), "r"(a2), "r"(a3), "r"(b0), "r"(b1));
}

// ---------------- transpose [CC][PP] -> [PP][CC] ----------------
__global__ void transpose_kernel(float* __restrict__ dst, const float* __restrict__ src) {
    __shared__ float t[32][33];
    int bx = blockIdx.x * 32, by = blockIdx.y * 32;
    int tx = threadIdx.x, ty = threadIdx.y;
    #pragma unroll
    for (int j = 0; j < 32; j += 8)
        t[ty + j][tx] = src[(size_t)(by + ty + j) * PP + bx + tx];
    __syncthreads();
    #pragma unroll
    for (int j = 0; j < 32; j += 8)
        dst[(size_t)(bx + ty + j) * CC + by + tx] = t[tx][ty + j];
}

// ---------------- precompute: fp16-hi fragment-ready ----------------
__global__ void splitA_kernel(const float* __restrict__ fl) {
    int idx = blockIdx.x * 256 + threadIdx.x;          // 196608
    int lane = idx & 31, mf = (idx >> 5) & 7, s = (idx >> 8) & 7, mt = idx >> 11;
    int g = lane >> 2, t = lane & 3;
    int M = mt * 128 + mf * 16 + g;
    int K = s * 16 + 2 * t;
    float v[8];
    v[0] = fl[(size_t)K * PP + M];           v[1] = fl[(size_t)(K + 1) * PP + M];
    v[2] = fl[(size_t)K * PP + M + 8];       v[3] = fl[(size_t)(K + 1) * PP + M + 8];
    v[4] = fl[(size_t)(K + 8) * PP + M];     v[5] = fl[(size_t)(K + 9) * PP + M];
    v[6] = fl[(size_t)(K + 8) * PP + M + 8]; v[7] = fl[(size_t)(K + 9) * PP + M + 8];
    uint4 o;
    o.x = ((uint32_t)h16(v[1]) << 16) | h16(v[0]);
    o.y = ((uint32_t)h16(v[3]) << 16) | h16(v[2]);
    o.z = ((uint32_t)h16(v[5]) << 16) | h16(v[4]);
    o.w = ((uint32_t)h16(v[7]) << 16) | h16(v[6]);
    gA4[((((size_t)mt * 8 + s) * 8 + mf)) * 32 + lane] = o;
}

__global__ void splitB_kernel(const float* __restrict__ fr) {
    int idx = blockIdx.x * 256 + threadIdx.x;          // 196608
    int lane = idx & 31, r4 = (idx >> 5) & 3, wn = (idx >> 7) & 3;
    int s = (idx >> 9) & 7, qt = idx >> 12;
    int g = lane >> 2, t = lane & 3;
    int k0 = s * 16 + 2 * t;
    uint32_t regs[4];
    #pragma unroll
    for (int h2 = 0; h2 < 2; ++h2) {
        int j = 2 * r4 + h2;
        int n = qt * 256 + wn * 64 + j * 8 + g;
        float v0 = fr[(size_t)k0 * QQ + n];
        float v1 = fr[(size_t)(k0 + 1) * QQ + n];
        float v8 = fr[(size_t)(k0 + 8) * QQ + n];
        float v9 = fr[(size_t)(k0 + 9) * QQ + n];
        regs[2 * h2]     = ((uint32_t)h16(v1) << 16) | h16(v0);
        regs[2 * h2 + 1] = ((uint32_t)h16(v9) << 16) | h16(v8);
    }
    size_t o = ((((size_t)qt * 8 + s) * 4 + wn) * 4 + r4) * 32 + lane;
    gB4[o] = make_uint4(regs[0], regs[1], regs[2], regs[3]);
}

__global__ void init_kernel() {
    if (blockIdx.x == 0 && threadIdx.x == 0) g_cnt = 0;
}

// ---------------- compute half (1 pass over 4 k-steps) ----------------
__device__ __forceinline__ void mma_block(float* acc, const uint4 af[4], const uint4 bfm[4]) {
    #pragma unroll
    for (int i = 0; i < 4; ++i) {
        #pragma unroll
        for (int r = 0; r < 4; ++r) {
            mma16816(&acc[(i * 8 + 2 * r) * 4],
                     af[i].x, af[i].y, af[i].z, af[i].w, bfm[r].x, bfm[r].y);
            mma16816(&acc[(i * 8 + 2 * r + 1) * 4],
                     af[i].x, af[i].y, af[i].z, af[i].w, bfm[r].z, bfm[r].w);
        }
    }
}

__device__ __forceinline__ void compute_half(const uint4* A0, const uint4* Bw, float* acc) {
    #pragma unroll
    for (int s = 0; s < 4; ++s) {
        uint4 bfm[4];
        const uint4* bp = Bw + (s << 9);
        #pragma unroll
        for (int r = 0; r < 4; ++r) bfm[r] = bp[r * 32];
        uint4 af[4];
        #pragma unroll
        for (int i = 0; i < 4; ++i) af[i] = A0[(s * 8 + i) * 32];
        mma_block(acc, af, bfm);
    }
}

// fold tile's acc into running per-slot top-2, zero acc
__device__ __forceinline__ void fold_zero(float* acc, float* bv, int* bq, float* bw,
                                          int q0, int t2) {
    #pragma unroll
    for (int i = 0; i < 4; ++i)
        #pragma unroll
        for (int j = 0; j < 8; ++j) {
            int qb = q0 + j * 8 + t2;
            #pragma unroll
            for (int c = 0; c < 4; ++c) {
                float v = acc[(i * 8 + j) * 4 + c];
                int slot = i * 2 + (c >> 1);
                int q = qb + (c & 1);
                if (v > bv[slot])      { bw[slot] = bv[slot]; bv[slot] = v; bq[slot] = q; }
                else if (v > bw[slot]) { bw[slot] = v; }
                acc[(i * 8 + j) * 4 + c] = 0.0f;
            }
        }
}

// ---------------- main GEMM (1-pass fp16) + top-2 argmax ----------------
__global__ void __launch_bounds__(256, 1)
corr_mma_kernel() {
    extern __shared__ char smem[];
    const uint32_t sb = smem_u32(smem);
    const int tid = threadIdx.x, lane = tid & 31, wid = tid >> 5;
    const int wm = wid >> 2, wn = wid & 3;
    const int g = lane >> 2, t = lane & 3;
    const int mt = blockIdx.x, ns = blockIdx.y;
    const int tile0 = ns * TPC;

    const uint32_t FULL0 = sb + 0,  FULL1 = sb + 16, FULL2 = sb + 32, FULL3 = sb + 48;
    const uint32_t FREE0 = sb + 64, FREE1 = sb + 80, FREE2 = sb + 96, FREE3 = sb + 112;
    if (tid == 0) {
        MBAR_INIT(FULL0, 1); MBAR_INIT(FULL1, 1); MBAR_INIT(FULL2, 1); MBAR_INIT(FULL3, 1);
        MBAR_INIT(FREE0, 256); MBAR_INIT(FREE1, 256);
        MBAR_INIT(FREE2, 256); MBAR_INIT(FREE3, 256);
    }

    // A image (32KB) -> resident SMEM
    {
        const uint4* srcA = gA4 + (size_t)mt * 2048;
        uint4* dstA = reinterpret_cast<uint4*>(smem + SMEM_A_OFF);
        #pragma unroll
        for (int i = 0; i < 8; ++i) dstA[i * 256 + tid] = srcA[i * 256 + tid];
    }
    __syncthreads();

    const char* gb = reinterpret_cast<const char*>(gB4);
    if (tid == 0) {
        size_t b0 = (size_t)tile0 * B_IMG_BYTES;
        issue_cp(sb + SMEM_B_OFF + 0 * B_HALF_BYTES, gb + b0,                               FULL0);
        issue_cp(sb + SMEM_B_OFF + 1 * B_HALF_BYTES, gb + b0 + B_HALF_BYTES,                FULL1);
        issue_cp(sb + SMEM_B_OFF + 2 * B_HALF_BYTES, gb + b0 + B_IMG_BYTES,                 FULL2);
        issue_cp(sb + SMEM_B_OFF + 3 * B_HALF_BYTES, gb + b0 + B_IMG_BYTES + B_HALF_BYTES,  FULL3);
    }

    const uint4* A0 = reinterpret_cast<const uint4*>(smem + SMEM_A_OFF) + (4 * wm) * 32 + lane;
    const uint4* B0 = reinterpret_cast<const uint4*>(smem + SMEM_B_OFF) + (wn << 7) + lane;
    const uint4* B1 = B0 + (B_HALF_BYTES / 16);
    const uint4* B2 = B1 + (B_HALF_BYTES / 16);
    const uint4* B3 = B2 + (B_HALF_BYTES / 16);

    float acc[128];
    float bv[8], bw[8];
    int bq[8];
    #pragma unroll
    for (int i = 0; i < 8; ++i) { bv[i] = -FLT_MAX; bw[i] = -FLT_MAX; bq[i] = 0; }

    const int t2 = 2 * t;

    for (int p8 = 0; p8 < 8; ++p8) {       // tile pair (2*p8, 2*p8+1)
        const uint32_t ph = (uint32_t)(p8 & 1);
        const int T0 = 2 * p8;
        const bool refill = (p8 < 7);
        const size_t nb0 = (size_t)(tile0 + T0 + 2) * B_IMG_BYTES;
        const size_t nb1 = nb0 + B_IMG_BYTES;

        if (p8 == 0) {
            #pragma unroll
            for (int i = 0; i < 128; ++i) acc[i] = 0.0f;
        } else {
            fold_zero(acc, bv, bq, bw, (tile0 + T0 - 1) * 256 + wn * 64, t2);
        }

        mbar_wait(FULL0, ph);
        compute_half(A0, B0, acc);
        MBAR_ARRIVE(FREE0);
        if (tid == 0 && refill) { mbar_wait(FREE0, ph);
            issue_cp(sb + SMEM_B_OFF + 0 * B_HALF_BYTES, gb + nb0, FULL0); }

        mbar_wait(FULL1, ph);
        compute_half(A0 + 1024, B1, acc);
        MBAR_ARRIVE(FREE1);
        if (tid == 0 && refill) { mbar_wait(FREE1, ph);
            issue_cp(sb + SMEM_B_OFF + 1 * B_HALF_BYTES, gb + nb0 + B_HALF_BYTES, FULL1); }

        fold_zero(acc, bv, bq, bw, (tile0 + T0) * 256 + wn * 64, t2);

        mbar_wait(FULL2, ph);
        compute_half(A0, B2, acc);
        MBAR_ARRIVE(FREE2);
        if (tid == 0 && refill) { mbar_wait(FREE2, ph);
            issue_cp(sb + SMEM_B_OFF + 2 * B_HALF_BYTES, gb + nb1, FULL2); }

        mbar_wait(FULL3, ph);
        compute_half(A0 + 1024, B3, acc);
        MBAR_ARRIVE(FREE3);
        if (tid == 0 && refill) { mbar_wait(FREE3, ph);
            issue_cp(sb + SMEM_B_OFF + 3 * B_HALF_BYTES, gb + nb1 + B_HALF_BYTES, FULL3); }
    }

    fold_zero(acc, bv, bq, bw, (tile0 + TPC - 1) * 256 + wn * 64, t2);

    // top-2 merge across the 4 lanes sharing each row
    #pragma unroll
    for (int off = 1; off < 4; off <<= 1) {
        #pragma unroll
        for (int s2 = 0; s2 < 8; ++s2) {
            float ov = __shfl_xor_sync(0xFFFFFFFFu, bv[s2], off);
            int oq = __shfl_xor_sync(0xFFFFFFFFu, bq[s2], off);
            float ow = __shfl_xor_sync(0xFFFFFFFFu, bw[s2], off);
            if (ov > bv[s2] || (ov == bv[s2] && oq < bq[s2])) {
                bw[s2] = fmaxf(bv[s2], ow); bv[s2] = ov; bq[s2] = oq;
            } else {
                bw[s2] = fmaxf(bw[s2], ov);
            }
        }
    }
    // one slot per (ns, wn, row) — exactly one writer
    if (t == 0) {
        #pragma unroll
        for (int s2 = 0; s2 < 8; ++s2) {
            int row = mt * 128 + (4 * wm + (s2 >> 1)) * 16 + g + (s2 & 1) * 8;
            g_part[((size_t)(ns * 4 + wn)) * PP + row] =
                make_float4(bv[s2], __int_as_float(bq[s2]), bw[s2], 0.0f);
        }
    }
}

// ---------------- decode1: merge 12 partials, exact winner, flag + scan-mask ----------------
__global__ void decode1_kernel(float* __restrict__ out,
                               const int* __restrict__ sxp,
                               const int* __restrict__ syp) {
    int p = blockIdx.x * 8 + (threadIdx.x >> 5);
    int lane = threadIdx.x & 31;

    float v1 = -FLT_MAX, v2 = -FLT_MAX, myz = -FLT_MAX;
    int q1 = 0x7FFFFFFF;
    if (lane < 12) {
        float4 pa = g_part[(size_t)lane * PP + p];
        v1 = pa.x; q1 = __float_as_int(pa.y); v2 = pa.z; myz = pa.z;
    }
    // reduce top-2-with-index across lanes 0..15
    #pragma unroll
    for (int off = 8; off; off >>= 1) {
        float ov1 = __shfl_down_sync(0xFFFFFFFFu, v1, off, 16);
        int   oq1 = __shfl_down_sync(0xFFFFFFFFu, q1, off, 16);
        float ov2 = __shfl_down_sync(0xFFFFFFFFu, v2, off, 16);
        if (ov1 > v1 || (ov1 == v1 && oq1 < q1)) {
            v2 = fmaxf(v1, ov2); v1 = ov1; q1 = oq1;
        } else {
            v2 = fmaxf(v2, ov1);
        }
    }
    float v1g = __shfl_sync(0xFFFFFFFFu, v1, 0);
    float v2g = __shfl_sync(0xFFFFFFFFu, v2, 0);
    int   q1g = __shfl_sync(0xFFFFFFFFu, q1, 0);
    // partitions whose runner-up could contain the true winner -> need range scan
    int mask = (int)(__ballot_sync(0xFFFFFFFFu, myz >= v1g - DELTA) & 0xFFFu);

    // exact fp32 dot for the winner (always; exact flow_cost)
    float4 a = *reinterpret_cast<const float4*>(gflT + (size_t)p * CC + lane * 4);
    float4 b = *reinterpret_cast<const float4*>(gfrT + (size_t)q1g * CC + lane * 4);
    float s = fmaf(a.x, b.x, fmaf(a.y, b.y, fmaf(a.z, b.z, a.w * b.w)));
    #pragma unroll
    for (int off = 16; off > 0; off >>= 1) s += __shfl_xor_sync(0xFFFFFFFFu, s, off);

    if (lane == 0) {
        int sx = sxp ? *sxp : 4;
        int sy = syp ? *syp : 4;
        int h = p / WW, w = p % WW;
        int i = q1g / WRR, j = q1g % WRR;
        out[2 * p + 0]  = (float)(w - j * sx);
        out[2 * p + 1]  = (float)(h - i * sy);
        out[2 * PP + p] = s;
        if (v1g - v2g < DELTA) {
            int k = atomicAdd(&g_cnt, 1);
            g_list[k] = p;
            g_mask[k] = mask;
        }
    }
}

// ---------------- repair: exact eval of 12 partition winners + flagged partition scans ----------------
__global__ void repair_kernel(const float* __restrict__ fr) {
    __shared__ float fls[128];
    __shared__ unsigned long long sbest;
    int cnt = g_cnt;
    int tid = threadIdx.x, lane = tid & 31, wid = tid >> 5;

    for (int r = blockIdx.x; r < cnt; r += gridDim.x) {
        int p = g_list[r];
        int mask = g_mask[r];
        __syncthreads();
        if (tid == 0) sbest = 0ull;
        if (tid < 32)
            *reinterpret_cast<float4*>(fls + tid * 4) =
                *reinterpret_cast<const float4*>(gflT + (size_t)p * CC + tid * 4);
        __syncthreads();

        // exact dots for all 12 partition winners (indices known)
        for (int k = wid; k < 12; k += 8) {
            float4 pa = g_part[(size_t)k * PP + p];
            int q = __float_as_int(pa.y);
            float4 a = *reinterpret_cast<const float4*>(fls + lane * 4);
            float4 b = *reinterpret_cast<const float4*>(gfrT + (size_t)q * CC + lane * 4);
            float s = fmaf(a.x, b.x, fmaf(a.y, b.y, fmaf(a.z, b.z, a.w * b.w)));
            #pragma unroll
            for (int off = 16; off > 0; off >>= 1) s += __shfl_xor_sync(0xFFFFFFFFu, s, off);
            if (lane == 0) atomicMax(&sbest, packkey(s, q));
        }

        // exact scans of flagged partitions (1024 q each)
        int m = mask;
        while (m) {
            int k = __ffs(m) - 1; m &= m - 1;
            int ns = k >> 2, wn = k & 3;
            int qarr[4];
            float acc0 = 0.f, acc1 = 0.f, acc2 = 0.f, acc3 = 0.f;
            #pragma unroll
            for (int i = 0; i < 4; ++i) {
                int idx = tid + i * 256;
                int tile = idx >> 6, j = idx & 63;
                qarr[i] = (ns * 16 + tile) * 256 + wn * 64 + j;
            }
            #pragma unroll 4
            for (int c = 0; c < 128; ++c) {
                float f = fls[c];
                const float* frc = fr + (size_t)c * QQ;
                acc0 = fmaf(f, frc[qarr[0]], acc0);
                acc1 = fmaf(f, frc[qarr[1]], acc1);
                acc2 = fmaf(f, frc[qarr[2]], acc2);
                acc3 = fmaf(f, frc[qarr[3]], acc3);
            }
            unsigned long long pk = packkey(acc0, qarr[0]);
            unsigned long long p1 = packkey(acc1, qarr[1]); if (p1 > pk) pk = p1;
            unsigned long long p2 = packkey(acc2, qarr[2]); if (p2 > pk) pk = p2;
            unsigned long long p3 = packkey(acc3, qarr[3]); if (p3 > pk) pk = p3;
            #pragma unroll
            for (int off = 16; off > 0; off >>= 1) {
                unsigned long long o = __shfl_xor_sync(0xFFFFFFFFu, pk, off);
                if (o > pk) pk = o;
            }
            if (lane == 0) atomicMax(&sbest, pk);
        }

        __syncthreads();
        if (tid == 0) g_best[p] = sbest;   // unique block per row -> plain store
    }
}

// ---------------- decode2: overwrite flagged rows with exact results ----------------
__global__ void decode2_kernel(float* __restrict__ out,
                               const int* __restrict__ sxp,
                               const int* __restrict__ syp) {
    int i = blockIdx.x * blockDim.x + threadIdx.x;
    if (i >= g_cnt) return;
    int p = g_list[i];
    int sx = sxp ? *sxp : 4;
    int sy = syp ? *syp : 4;

    unsigned long long pk = g_best[p];
    unsigned int key = (unsigned int)(pk >> 32);
    unsigned int idx = 0xFFFFFFFFu - (unsigned int)(pk & 0xFFFFFFFFu);
    float val = (key & 0x80000000u) ? __uint_as_float(key ^ 0x80000000u)
                                    : __uint_as_float(~key);
    int h = p / WW, w = p % WW;
    int ii = (int)(idx / WRR), j = (int)(idx % WRR);

    out[2 * p + 0]  = (float)(w - j * sx);
    out[2 * p + 1]  = (float)(h - ii * sy);
    out[2 * PP + p] = val;
}

// ---------------- launch ----------------
extern "C" void kernel_launch(void* const* d_in, const int* in_sizes, int n_in,
                              void* d_out, int out_size) {
    const float* fl = (const float*)d_in[0];
    const float* fr = (const float*)d_in[1];
    const int* sxp = (n_in > 2) ? (const int*)d_in[2] : nullptr;
    const int* syp = (n_in > 3) ? (const int*)d_in[3] : nullptr;
    float* out = (float*)d_out;
    (void)in_sizes; (void)out_size;

    cudaFuncSetAttribute(corr_mma_kernel,
                         cudaFuncAttributeMaxDynamicSharedMemorySize, SMEM_TOTAL);

    float* flT; cudaGetSymbolAddress((void**)&flT, gflT);
    float* frT; cudaGetSymbolAddress((void**)&frT, gfrT);

    transpose_kernel<<<dim3(PP / 32, CC / 32), dim3(32, 8)>>>(flT, fl);
    transpose_kernel<<<dim3(QQ / 32, CC / 32), dim3(32, 8)>>>(frT, fr);
    splitA_kernel<<<768, 256>>>(fl);
    splitB_kernel<<<768, 256>>>(fr);
    init_kernel<<<1, 32>>>();
    corr_mma_kernel<<<dim3(PP / BM, NS), 256, SMEM_TOTAL>>>();
    decode1_kernel<<<PP / 8, 256>>>(out, sxp, syp);
    repair_kernel<<<1024, 256>>>(fr);
    decode2_kernel<<<48, 256>>>(out, sxp, syp);
}

// round 16
// speedup vs baseline: 2.9644x; 1.1332x over previous
#include <cuda_runtime.h>
#include <cuda_fp16.h>
#include <cstdint>
#include <cfloat>

// ---------------- problem constants ----------------
#define CC   128
#define HH   96
#define WW   128
#define PP   (HH * WW)      // 12288 (M)
#define HRR  96
#define WRR  128
#define QQ   (HRR * WRR)    // 12288 (N)

// ---------------- tiling ----------------
#define BM    128
#define BN    256
#define NQT   (QQ / BN)     // 48
#define NS    3             // 288 CTAs = 2 waves @ 94.7%
#define TPC   (NQT / NS)    // 16 tiles per CTA

#define A_IMG_BYTES   32768
#define B_IMG_BYTES   65536
#define SMEM_A_OFF    1024
#define SMEM_B0_OFF   (SMEM_A_OFF + A_IMG_BYTES)           // 33792
#define SMEM_B1_OFF   (SMEM_B0_OFF + B_IMG_BYTES)          // 99328
#define SMEM_TOTAL    (SMEM_B1_OFF + B_IMG_BYTES)          // 164864

#define DELTA 0.10f

// ---------------- device scratch (no allocs allowed) ----------------
__device__ uint4 gA4[96 * 8 * 8 * 32];            // fp16-hi A fragments
__device__ uint4 gB4[48 * 8 * 4 * 4 * 32];        // fp16-hi B fragments (1 variant, 3MB)
__device__ float gflT[(size_t)PP * CC];
__device__ float gfrT[(size_t)QQ * CC];
// per-(split,wn) approx top-2: {v1, q1-as-float-bits, v2, 0} — one writer per slot
__device__ float4 g_part[NS * 4 * PP];
__device__ int g_cnt;
__device__ int g_list[PP];
__device__ int g_mask[PP];
__device__ unsigned long long g_best[PP];

// ---------------- helpers ----------------
__device__ __forceinline__ uint32_t smem_u32(const void* p) {
    uint32_t a;
    asm("{ .reg .u64 t; cvta.to.shared.u64 t, %1; cvt.u32.u64 %0, t; }" : "=r"(a) : "l"(p));
    return a;
}
__device__ __forceinline__ unsigned int fkey(float f) {
    unsigned int b = __float_as_uint(f);
    return (b & 0x80000000u) ? ~b : (b | 0x80000000u);
}
__device__ __forceinline__ unsigned long long packkey(float v, int q) {
    return ((unsigned long long)fkey(v) << 32) | (0xFFFFFFFFu - (unsigned)q);
}
__device__ __forceinline__ unsigned short h16(float x) {
    __half h = __float2half_rn(x);
    return *reinterpret_cast<unsigned short*>(&h);
}

// ---------------- mbarrier ----------------
#define MBAR_INIT(a, n) \
    asm volatile("mbarrier.init.shared.b64 [%0], %1;" :: "r"(a), "r"((uint32_t)(n)) : "memory")
#define MBAR_EXPECT_TX(a, n) \
    asm volatile("mbarrier.arrive.expect_tx.shared.b64 _, [%0], %1;" :: "r"(a), "r"((uint32_t)(n)) : "memory")
#define MBAR_ARRIVE(a) \
    asm volatile("mbarrier.arrive.shared.b64 _, [%0];" :: "r"(a) : "memory")

__device__ __forceinline__ void mbar_wait(uint32_t mbar, uint32_t phase) {
    asm volatile(
        "{\n\t.reg .pred P1;\n\t"
        "W_%=:\n\t"
        "mbarrier.try_wait.parity.acquire.cta.shared::cta.b64 P1, [%0], %1, 0x989680;\n\t"
        "@P1 bra.uni D_%=;\n\t"
        "bra.uni W_%=;\n\t"
        "D_%=:\n\t}"
        :: "r"(mbar), "r"(phase) : "memory");
}

__device__ __forceinline__ void issue_cp(uint32_t dst, const char* src, uint32_t fullb) {
    MBAR_EXPECT_TX(fullb, B_IMG_BYTES);
    asm volatile(
        "cp.async.bulk.shared::cluster.global.mbarrier::complete_tx::bytes "
        "[%0], [%1], %2, [%3];"
        :: "r"(dst), "l"(src), "r"((uint32_t)B_IMG_BYTES), "r"(fullb) : "memory");
}

// ---------------- legacy tensor-core mma ----------------
__device__ __forceinline__ void mma16816(float* d, uint32_t a0, uint32_t a1, uint32_t a2,
                                         uint32_t a3, uint32_t b0, uint32_t b1) {
    asm volatile(
        "mma.sync.aligned.m16n8k16.row.col.f32.f16.f16.f32 "
        "{%0,%1,%2,%3}, {%4,%5,%6,%7}, {%8,%9}, {%0,%1,%2,%3};"
        : "+f"(d[0]), "+f"(d[1]), "+f"(d[2]), "+f"(d[3])
        : "r"(a0), "r"(a1), "r"(a2), "r"(a3), "r"(b0), "r"(b1));
}

// ---------------- transpose [CC][PP] -> [PP][CC] ----------------
__global__ void transpose_kernel(float* __restrict__ dst, const float* __restrict__ src) {
    __shared__ float t[32][33];
    int bx = blockIdx.x * 32, by = blockIdx.y * 32;
    int tx = threadIdx.x, ty = threadIdx.y;
    #pragma unroll
    for (int j = 0; j < 32; j += 8)
        t[ty + j][tx] = src[(size_t)(by + ty + j) * PP + bx + tx];
    __syncthreads();
    #pragma unroll
    for (int j = 0; j < 32; j += 8)
        dst[(size_t)(bx + ty + j) * CC + by + tx] = t[tx][ty + j];
}

// ---------------- precompute: fp16-hi fragment-ready ----------------
__global__ void splitA_kernel(const float* __restrict__ fl) {
    int idx = blockIdx.x * 256 + threadIdx.x;          // 196608
    int lane = idx & 31, mf = (idx >> 5) & 7, s = (idx >> 8) & 7, mt = idx >> 11;
    int g = lane >> 2, t = lane & 3;
    int M = mt * 128 + mf * 16 + g;
    int K = s * 16 + 2 * t;
    float v[8];
    v[0] = fl[(size_t)K * PP + M];           v[1] = fl[(size_t)(K + 1) * PP + M];
    v[2] = fl[(size_t)K * PP + M + 8];       v[3] = fl[(size_t)(K + 1) * PP + M + 8];
    v[4] = fl[(size_t)(K + 8) * PP + M];     v[5] = fl[(size_t)(K + 9) * PP + M];
    v[6] = fl[(size_t)(K + 8) * PP + M + 8]; v[7] = fl[(size_t)(K + 9) * PP + M + 8];
    uint4 o;
    o.x = ((uint32_t)h16(v[1]) << 16) | h16(v[0]);
    o.y = ((uint32_t)h16(v[3]) << 16) | h16(v[2]);
    o.z = ((uint32_t)h16(v[5]) << 16) | h16(v[4]);
    o.w = ((uint32_t)h16(v[7]) << 16) | h16(v[6]);
    gA4[((((size_t)mt * 8 + s) * 8 + mf)) * 32 + lane] = o;
}

__global__ void splitB_kernel(const float* __restrict__ fr) {
    int idx = blockIdx.x * 256 + threadIdx.x;          // 196608
    int lane = idx & 31, r4 = (idx >> 5) & 3, wn = (idx >> 7) & 3;
    int s = (idx >> 9) & 7, qt = idx >> 12;
    int g = lane >> 2, t = lane & 3;
    int k0 = s * 16 + 2 * t;
    uint32_t regs[4];
    #pragma unroll
    for (int h2 = 0; h2 < 2; ++h2) {
        int j = 2 * r4 + h2;
        int n = qt * 256 + wn * 64 + j * 8 + g;
        float v0 = fr[(size_t)k0 * QQ + n];
        float v1 = fr[(size_t)(k0 + 1) * QQ + n];
        float v8 = fr[(size_t)(k0 + 8) * QQ + n];
        float v9 = fr[(size_t)(k0 + 9) * QQ + n];
        regs[2 * h2]     = ((uint32_t)h16(v1) << 16) | h16(v0);
        regs[2 * h2 + 1] = ((uint32_t)h16(v9) << 16) | h16(v8);
    }
    size_t o = ((((size_t)qt * 8 + s) * 4 + wn) * 4 + r4) * 32 + lane;
    gB4[o] = make_uint4(regs[0], regs[1], regs[2], regs[3]);
}

__global__ void init_kernel() {
    if (blockIdx.x == 0 && threadIdx.x == 0) g_cnt = 0;
}

// ---------------- full-tile compute (1 pass over 8 k-steps, 256 MMAs/warp) ----------------
__device__ __forceinline__ void mma_block(float* acc, const uint4 af[4], const uint4 bfm[4]) {
    #pragma unroll
    for (int i = 0; i < 4; ++i) {
        #pragma unroll
        for (int r = 0; r < 4; ++r) {
            mma16816(&acc[(i * 8 + 2 * r) * 4],
                     af[i].x, af[i].y, af[i].z, af[i].w, bfm[r].x, bfm[r].y);
            mma16816(&acc[(i * 8 + 2 * r + 1) * 4],
                     af[i].x, af[i].y, af[i].z, af[i].w, bfm[r].z, bfm[r].w);
        }
    }
}

__device__ __forceinline__ void compute_tile(const uint4* A0, const uint4* Bw, float* acc) {
    #pragma unroll
    for (int s = 0; s < 8; ++s) {
        uint4 bfm[4];
        const uint4* bp = Bw + (s << 9);
        #pragma unroll
        for (int r = 0; r < 4; ++r) bfm[r] = bp[r * 32];
        uint4 af[4];
        #pragma unroll
        for (int i = 0; i < 4; ++i) af[i] = A0[(s * 8 + i) * 32];
        mma_block(acc, af, bfm);
    }
}

// fold tile's acc into running per-slot top-2, zero acc
__device__ __forceinline__ void fold_zero(float* acc, float* bv, int* bq, float* bw,
                                          int q0, int t2) {
    #pragma unroll
    for (int i = 0; i < 4; ++i)
        #pragma unroll
        for (int j = 0; j < 8; ++j) {
            int qb = q0 + j * 8 + t2;
            #pragma unroll
            for (int c = 0; c < 4; ++c) {
                float v = acc[(i * 8 + j) * 4 + c];
                int slot = i * 2 + (c >> 1);
                int q = qb + (c & 1);
                if (v > bv[slot])      { bw[slot] = bv[slot]; bv[slot] = v; bq[slot] = q; }
                else if (v > bw[slot]) { bw[slot] = v; }
                acc[(i * 8 + j) * 4 + c] = 0.0f;
            }
        }
}

// ---------------- main GEMM (1-pass fp16, R10-shaped pipeline) + top-2 argmax ----------------
__global__ void __launch_bounds__(256, 1)
corr_mma_kernel() {
    extern __shared__ char smem[];
    const uint32_t sb = smem_u32(smem);
    const int tid = threadIdx.x, lane = tid & 31, wid = tid >> 5;
    const int wm = wid >> 2, wn = wid & 3;
    const int g = lane >> 2, t = lane & 3;
    const int mt = blockIdx.x, ns = blockIdx.y;
    const int tile0 = ns * TPC;

    const uint32_t FULL0 = sb + 0,  FULL1 = sb + 16;
    const uint32_t FREE0 = sb + 32, FREE1 = sb + 48;
    if (tid == 0) {
        MBAR_INIT(FULL0, 1); MBAR_INIT(FULL1, 1);
        MBAR_INIT(FREE0, 256); MBAR_INIT(FREE1, 256);
    }

    // A image (32KB) -> resident SMEM, coalesced
    {
        const uint4* srcA = gA4 + (size_t)mt * 2048;
        uint4* dstA = reinterpret_cast<uint4*>(smem + SMEM_A_OFF);
        #pragma unroll
        for (int i = 0; i < 8; ++i) dstA[i * 256 + tid] = srcA[i * 256 + tid];
    }
    __syncthreads();   // barriers init + A visible

    const char* gb = reinterpret_cast<const char*>(gB4);
    // prologue: buf0 = tile0, buf1 = tile0+1
    if (tid == 0) {
        issue_cp(sb + SMEM_B0_OFF, gb + (size_t)tile0 * B_IMG_BYTES, FULL0);
        issue_cp(sb + SMEM_B1_OFF, gb + (size_t)(tile0 + 1) * B_IMG_BYTES, FULL1);
    }

    const uint4* A0 = reinterpret_cast<const uint4*>(smem + SMEM_A_OFF) + (4 * wm) * 32 + lane;
    const uint4* Bw0 = reinterpret_cast<const uint4*>(smem + SMEM_B0_OFF) + (wn << 7) + lane;
    const uint4* Bw1 = reinterpret_cast<const uint4*>(smem + SMEM_B1_OFF) + (wn << 7) + lane;

    float acc[128];
    float bv[8], bw[8];
    int bq[8];
    #pragma unroll
    for (int i = 0; i < 8; ++i) { bv[i] = -FLT_MAX; bw[i] = -FLT_MAX; bq[i] = 0; }

    const int t2 = 2 * t;

    for (int tile = 0; tile < TPC; ++tile) {
        const int b = tile & 1;
        const uint32_t ph = (uint32_t)((tile >> 1) & 1);
        const uint32_t FULLB = b ? FULL1 : FULL0;
        const uint32_t FREEB = b ? FREE1 : FREE0;

        // deferred fold of previous tile (or first-time zero) hides under wait/MMA shadow
        if (tile == 0) {
            #pragma unroll
            for (int i = 0; i < 128; ++i) acc[i] = 0.0f;
        } else {
            fold_zero(acc, bv, bq, bw, (tile0 + tile - 1) * 256 + wn * 64, t2);
        }

        mbar_wait(FULLB, ph);
        compute_tile(A0, b ? Bw1 : Bw0, acc);
        MBAR_ARRIVE(FREEB);

        if (tid == 0 && tile + 2 < TPC) {
            mbar_wait(FREEB, ph);
            issue_cp(sb + (b ? SMEM_B1_OFF : SMEM_B0_OFF),
                     gb + (size_t)(tile0 + tile + 2) * B_IMG_BYTES, FULLB);
        }
    }

    fold_zero(acc, bv, bq, bw, (tile0 + TPC - 1) * 256 + wn * 64, t2);

    // top-2 merge across the 4 lanes sharing each row
    #pragma unroll
    for (int off = 1; off < 4; off <<= 1) {
        #pragma unroll
        for (int s2 = 0; s2 < 8; ++s2) {
            float ov = __shfl_xor_sync(0xFFFFFFFFu, bv[s2], off);
            int oq = __shfl_xor_sync(0xFFFFFFFFu, bq[s2], off);
            float ow = __shfl_xor_sync(0xFFFFFFFFu, bw[s2], off);
            if (ov > bv[s2] || (ov == bv[s2] && oq < bq[s2])) {
                bw[s2] = fmaxf(bv[s2], ow); bv[s2] = ov; bq[s2] = oq;
            } else {
                bw[s2] = fmaxf(bw[s2], ov);
            }
        }
    }
    // one slot per (ns, wn, row) — exactly one writer
    if (t == 0) {
        #pragma unroll
        for (int s2 = 0; s2 < 8; ++s2) {
            int row = mt * 128 + (4 * wm + (s2 >> 1)) * 16 + g + (s2 & 1) * 8;
            g_part[((size_t)(ns * 4 + wn)) * PP + row] =
                make_float4(bv[s2], __int_as_float(bq[s2]), bw[s2], 0.0f);
        }
    }
}

// ---------------- decode1: merge 12 partials, exact winner, flag + scan-mask ----------------
__global__ void decode1_kernel(float* __restrict__ out,
                               const int* __restrict__ sxp,
                               const int* __restrict__ syp) {
    int p = blockIdx.x * 8 + (threadIdx.x >> 5);
    int lane = threadIdx.x & 31;

    float v1 = -FLT_MAX, v2 = -FLT_MAX, myz = -FLT_MAX;
    int q1 = 0x7FFFFFFF;
    if (lane < 12) {
        float4 pa = g_part[(size_t)lane * PP + p];
        v1 = pa.x; q1 = __float_as_int(pa.y); v2 = pa.z; myz = pa.z;
    }
    #pragma unroll
    for (int off = 8; off; off >>= 1) {
        float ov1 = __shfl_down_sync(0xFFFFFFFFu, v1, off, 16);
        int   oq1 = __shfl_down_sync(0xFFFFFFFFu, q1, off, 16);
        float ov2 = __shfl_down_sync(0xFFFFFFFFu, v2, off, 16);
        if (ov1 > v1 || (ov1 == v1 && oq1 < q1)) {
            v2 = fmaxf(v1, ov2); v1 = ov1; q1 = oq1;
        } else {
            v2 = fmaxf(v2, ov1);
        }
    }
    float v1g = __shfl_sync(0xFFFFFFFFu, v1, 0);
    float v2g = __shfl_sync(0xFFFFFFFFu, v2, 0);
    int   q1g = __shfl_sync(0xFFFFFFFFu, q1, 0);
    int mask = (int)(__ballot_sync(0xFFFFFFFFu, myz >= v1g - DELTA) & 0xFFFu);

    // exact fp32 dot for the winner (always; exact flow_cost)
    float4 a = *reinterpret_cast<const float4*>(gflT + (size_t)p * CC + lane * 4);
    float4 b = *reinterpret_cast<const float4*>(gfrT + (size_t)q1g * CC + lane * 4);
    float s = fmaf(a.x, b.x, fmaf(a.y, b.y, fmaf(a.z, b.z, a.w * b.w)));
    #pragma unroll
    for (int off = 16; off > 0; off >>= 1) s += __shfl_xor_sync(0xFFFFFFFFu, s, off);

    if (lane == 0) {
        int sx = sxp ? *sxp : 4;
        int sy = syp ? *syp : 4;
        int h = p / WW, w = p % WW;
        int i = q1g / WRR, j = q1g % WRR;
        out[2 * p + 0]  = (float)(w - j * sx);
        out[2 * p + 1]  = (float)(h - i * sy);
        out[2 * PP + p] = s;
        if (v1g - v2g < DELTA) {
            int k = atomicAdd(&g_cnt, 1);
            g_list[k] = p;
            g_mask[k] = mask;
        }
    }
}

// ---------------- repair: exact eval of 12 partition winners + flagged partition scans ----------------
__global__ void repair_kernel(const float* __restrict__ fr) {
    __shared__ float fls[128];
    __shared__ unsigned long long sbest;
    int cnt = g_cnt;
    int tid = threadIdx.x, lane = tid & 31, wid = tid >> 5;

    for (int r = blockIdx.x; r < cnt; r += gridDim.x) {
        int p = g_list[r];
        int mask = g_mask[r];
        __syncthreads();
        if (tid == 0) sbest = 0ull;
        if (tid < 32)
            *reinterpret_cast<float4*>(fls + tid * 4) =
                *reinterpret_cast<const float4*>(gflT + (size_t)p * CC + tid * 4);
        __syncthreads();

        // exact dots for all 12 partition winners (indices known)
        for (int k = wid; k < 12; k += 8) {
            float4 pa = g_part[(size_t)k * PP + p];
            int q = __float_as_int(pa.y);
            float4 a = *reinterpret_cast<const float4*>(fls + lane * 4);
            float4 b = *reinterpret_cast<const float4*>(gfrT + (size_t)q * CC + lane * 4);
            float s = fmaf(a.x, b.x, fmaf(a.y, b.y, fmaf(a.z, b.z, a.w * b.w)));
            #pragma unroll
            for (int off = 16; off > 0; off >>= 1) s += __shfl_xor_sync(0xFFFFFFFFu, s, off);
            if (lane == 0) atomicMax(&sbest, packkey(s, q));
        }

        // exact scans of flagged partitions (1024 q each)
        int m = mask;
        while (m) {
            int k = __ffs(m) - 1; m &= m - 1;
            int ns = k >> 2, wn = k & 3;
            int qarr[4];
            float acc0 = 0.f, acc1 = 0.f, acc2 = 0.f, acc3 = 0.f;
            #pragma unroll
            for (int i = 0; i < 4; ++i) {
                int idx = tid + i * 256;
                int tile = idx >> 6, j = idx & 63;
                qarr[i] = (ns * 16 + tile) * 256 + wn * 64 + j;
            }
            #pragma unroll 4
            for (int c = 0; c < 128; ++c) {
                float f = fls[c];
                const float* frc = fr + (size_t)c * QQ;
                acc0 = fmaf(f, frc[qarr[0]], acc0);
                acc1 = fmaf(f, frc[qarr[1]], acc1);
                acc2 = fmaf(f, frc[qarr[2]], acc2);
                acc3 = fmaf(f, frc[qarr[3]], acc3);
            }
            unsigned long long pk = packkey(acc0, qarr[0]);
            unsigned long long p1 = packkey(acc1, qarr[1]); if (p1 > pk) pk = p1;
            unsigned long long p2 = packkey(acc2, qarr[2]); if (p2 > pk) pk = p2;
            unsigned long long p3 = packkey(acc3, qarr[3]); if (p3 > pk) pk = p3;
            #pragma unroll
            for (int off = 16; off > 0; off >>= 1) {
                unsigned long long o = __shfl_xor_sync(0xFFFFFFFFu, pk, off);
                if (o > pk) pk = o;
            }
            if (lane == 0) atomicMax(&sbest, pk);
        }

        __syncthreads();
        if (tid == 0) g_best[p] = sbest;   // unique block per row -> plain store
    }
}

// ---------------- decode2: overwrite flagged rows with exact results ----------------
__global__ void decode2_kernel(float* __restrict__ out,
                               const int* __restrict__ sxp,
                               const int* __restrict__ syp) {
    int i = blockIdx.x * blockDim.x + threadIdx.x;
    if (i >= g_cnt) return;
    int p = g_list[i];
    int sx = sxp ? *sxp : 4;
    int sy = syp ? *syp : 4;

    unsigned long long pk = g_best[p];
    unsigned int key = (unsigned int)(pk >> 32);
    unsigned int idx = 0xFFFFFFFFu - (unsigned int)(pk & 0xFFFFFFFFu);
    float val = (key & 0x80000000u) ? __uint_as_float(key ^ 0x80000000u)
                                    : __uint_as_float(~key);
    int h = p / WW, w = p % WW;
    int ii = (int)(idx / WRR), j = (int)(idx % WRR);

    out[2 * p + 0]  = (float)(w - j * sx);
    out[2 * p + 1]  = (float)(h - ii * sy);
    out[2 * PP + p] = val;
}

// ---------------- launch ----------------
extern "C" void kernel_launch(void* const* d_in, const int* in_sizes, int n_in,
                              void* d_out, int out_size) {
    const float* fl = (const float*)d_in[0];
    const float* fr = (const float*)d_in[1];
    const int* sxp = (n_in > 2) ? (const int*)d_in[2] : nullptr;
    const int* syp = (n_in > 3) ? (const int*)d_in[3] : nullptr;
    float* out = (float*)d_out;
    (void)in_sizes; (void)out_size;

    cudaFuncSetAttribute(corr_mma_kernel,
                         cudaFuncAttributeMaxDynamicSharedMemorySize, SMEM_TOTAL);

    float* flT; cudaGetSymbolAddress((void**)&flT, gflT);
    float* frT; cudaGetSymbolAddress((void**)&frT, gfrT);

    transpose_kernel<<<dim3(PP / 32, CC / 32), dim3(32, 8)>>>(flT, fl);
    transpose_kernel<<<dim3(QQ / 32, CC / 32), dim3(32, 8)>>>(frT, fr);
    splitA_kernel<<<768, 256>>>(fl);
    splitB_kernel<<<768, 256>>>(fr);
    init_kernel<<<1, 32>>>();
    corr_mma_kernel<<<dim3(PP / BM, NS), 256, SMEM_TOTAL>>>();
    decode1_kernel<<<PP / 8, 256>>>(out, sxp, syp);
    repair_kernel<<<2048, 256>>>(fr);
    decode2_kernel<<<48, 256>>>(out, sxp, syp);
}